// round 16
// baseline (speedup 1.0000x reference)
#include <cuda_runtime.h>
#include <cuda_fp16.h>
#include <cstdint>
#include <cstddef>

#define DM 1024
#define HEADS 16
#define HD 64
#define B_ 2
#define S_ 2048
#define MTOT 4096   // B*S

// ---------------------------------------------------------------------------
// Scratch (__device__ globals). q/k/v/ctx stored COMPACTED (active rows only).
// ---------------------------------------------------------------------------
__device__ __half g_x[MTOT * DM];
__device__ __half g_q[MTOT * DM];   // pre-scaled by 1/8
__device__ __half g_k[MTOT * DM];
__device__ __half g_v[MTOT * DM];
__device__ __half g_c[MTOT * DM];
__device__ __half g_w[4][DM * DM];  // W^T, [n][k]
__device__ int g_nact[B_];
__device__ int g_idx[B_ * S_];

// ---------------------------------------------------------------------------
// sm_100-safe PTX helpers
// ---------------------------------------------------------------------------
__device__ __forceinline__ uint32_t smem_u32(const void* p) {
    uint32_t a;
    asm("{ .reg .u64 t; cvta.to.shared.u64 t, %1; cvt.u32.u64 %0, t; }"
        : "=r"(a) : "l"(p));
    return a;
}
__device__ __forceinline__ void ldsm_x4(uint32_t* r, uint32_t addr) {
    asm volatile("ldmatrix.sync.aligned.m8n8.x4.shared.b16 {%0,%1,%2,%3}, [%4];"
                 : "=r"(r[0]), "=r"(r[1]), "=r"(r[2]), "=r"(r[3]) : "r"(addr));
}
__device__ __forceinline__ void ldsm_x4t(uint32_t* r, uint32_t addr) {
    asm volatile("ldmatrix.sync.aligned.m8n8.x4.trans.shared.b16 {%0,%1,%2,%3}, [%4];"
                 : "=r"(r[0]), "=r"(r[1]), "=r"(r[2]), "=r"(r[3]) : "r"(addr));
}
__device__ __forceinline__ void mma_f16(float* d, const uint32_t* a, const uint32_t* b) {
    asm volatile(
        "mma.sync.aligned.m16n8k16.row.col.f32.f16.f16.f32 "
        "{%0,%1,%2,%3},{%4,%5,%6,%7},{%8,%9},{%0,%1,%2,%3};"
        : "+f"(d[0]), "+f"(d[1]), "+f"(d[2]), "+f"(d[3])
        : "r"(a[0]), "r"(a[1]), "r"(a[2]), "r"(a[3]), "r"(b[0]), "r"(b[1]));
}
__device__ __forceinline__ void cp16(uint32_t s, const void* g) {
    asm volatile("cp.async.cg.shared.global [%0], [%1], 16;" :: "r"(s), "l"(g));
}
#define CP_COMMIT() asm volatile("cp.async.commit_group;" ::: "memory")
#define CP_WAIT0()  asm volatile("cp.async.wait_group 0;" ::: "memory")
#define CP_WAIT1()  asm volatile("cp.async.wait_group 1;" ::: "memory")

__device__ __forceinline__ uint32_t pack2h(float lo, float hi) {
    uint32_t r;
    asm("cvt.rn.f16x2.f32 %0, %1, %2;" : "=r"(r) : "f"(hi), "f"(lo));
    return r;
}

// ---------------------------------------------------------------------------
// Fused prologue: one launch, 8194 CTAs x 256 threads.
//   bid in [0,4096):    conv_w   (z = bid>>10, tile = bid&1023)
//   bid in [4096,8192): conv_x   (+ out = x copy)
//   bid in [8192,8194): build_idx (b = bid-8192)
// ---------------------------------------------------------------------------
__global__ __launch_bounds__(256) void prologue(
    const float* __restrict__ x, float* __restrict__ out,
    const int* __restrict__ gate,
    const float* __restrict__ W0, const float* __restrict__ W1,
    const float* __restrict__ W2, const float* __restrict__ W3)
{
    const int bid = blockIdx.x;
    const int tid = threadIdx.x;

    if (bid < 4096) {
        __shared__ float t[32][33];
        const int z = bid >> 10;
        const int tile = bid & 1023;
        const float* W = (z == 0) ? W0 : (z == 1) ? W1 : (z == 2) ? W2 : W3;
        const int n0 = (tile & 31) * 32;
        const int k0 = (tile >> 5) * 32;
        const int tx = tid & 31, ty = tid >> 5;
#pragma unroll
        for (int i = 0; i < 4; i++)
            t[ty + i * 8][tx] = W[(size_t)(k0 + ty + i * 8) * DM + n0 + tx];
        __syncthreads();
        __half* p = g_w[z];
#pragma unroll
        for (int i = 0; i < 4; i++)
            p[(size_t)(n0 + ty + i * 8) * DM + k0 + tx] =
                __float2half(t[tx][ty + i * 8]);
    } else if (bid < 8192) {
        const int i = ((bid - 4096) * 256 + tid) * 4;
        float4 v = *(const float4*)(x + i);
        *(float4*)(out + i) = v;
        *(__half2*)(g_x + i)     = __floats2half2_rn(v.x, v.y);
        *(__half2*)(g_x + i + 2) = __floats2half2_rn(v.z, v.w);
    } else {
        __shared__ int cnt[256];
        const int b = bid - 8192;
        const int base = b * S_ + tid * 8;
        int gv[8];
        int c = 0;
#pragma unroll
        for (int i = 0; i < 8; i++) { gv[i] = gate[base + i]; c += gv[i]; }
        cnt[tid] = c;
        __syncthreads();
        for (int off = 1; off < 256; off <<= 1) {
            int t = (tid >= off) ? cnt[tid - off] : 0;
            __syncthreads();
            cnt[tid] += t;
            __syncthreads();
        }
        int o = cnt[tid] - c;
        if (tid == 255) g_nact[b] = cnt[255];
#pragma unroll
        for (int i = 0; i < 8; i++)
            if (gv[i]) g_idx[b * S_ + (o++)] = tid * 8 + i;
    }
}

// ---------------------------------------------------------------------------
// fp16 HMMA GEMM, QKV (MODE-0 only now) — exact R9 config (measured best).
// CTA tile 128x128, 8 warps (2x4), warp tile 64x32, BK=32, pitch 80B.
// grid = (DM/128, B_*16, 3); y = batch*16 + jtile; z = q/k/v.
// ---------------------------------------------------------------------------
#define TILE_B 10240
#define STAGE_B (2 * TILE_B)              // 20480
#define GSMEM_TOT (2 * STAGE_B)           // 40960

__global__ __launch_bounds__(256, 2) void gemm_qkv(
    const float* __restrict__ bias0, const float* __restrict__ bias1,
    const float* __restrict__ bias2)
{
    extern __shared__ char smem[];
    const uint32_t sb = smem_u32(smem);
    const int tid = threadIdx.x;
    const int wid = tid >> 5;
    const int lane = tid & 31;
    const int wm = wid >> 2;
    const int wn = wid & 3;
    const int n0 = blockIdx.x * 128;

    const int bb = blockIdx.y >> 4;
    const int jbase = (blockIdx.y & 15) * 128;
    const int nact = g_nact[bb];
    if (jbase >= nact) return;
    const int z = blockIdx.z;

    const __half* Bw = g_w[z];
    const float* bias = (z == 0) ? bias0 : (z == 1) ? bias1 : bias2;
    __half* Oq = (z == 0) ? g_q : (z == 1) ? g_k : g_v;

    float acc[4][4][4];
#pragma unroll
    for (int i = 0; i < 4; i++)
#pragma unroll
        for (int j = 0; j < 4; j++)
#pragma unroll
            for (int e = 0; e < 4; e++) acc[i][j][e] = 0.f;

    const int lrow = tid >> 1;
    const int lc0 = (tid & 1) * 2;

    size_t rowA;
    {
        int j = jbase + lrow;
        if (j >= nact) j = nact - 1;
        rowA = (size_t)(bb * S_ + g_idx[bb * S_ + j]) * DM;
    }
    const size_t rowB = (size_t)(n0 + lrow) * DM;

    auto load_stage = [&](int st, int kc) {
        const int k0 = kc * 32;
        const uint32_t sbase = sb + st * STAGE_B;
#pragma unroll
        for (int c = 0; c < 2; c++) {
            const int ch = lc0 + c;
            const uint32_t so = lrow * 80 + ch * 16;
            cp16(sbase + so,          g_x + rowA + k0 + ch * 8);
            cp16(sbase + TILE_B + so, Bw + rowB + k0 + ch * 8);
        }
    };

    const int aRowOff = lane & 15;
    const int aColB0 = ((lane >> 4) << 3) * 2;
    const int bRowOff = (lane & 7) + ((lane >> 4) << 3);
    const int bColB0 = (((lane >> 3) & 1) << 3) * 2;

    load_stage(0, 0);
    CP_COMMIT();
    CP_WAIT0();
    __syncthreads();

    const int NCH = DM / 32;
    for (int kc = 0; kc < NCH; kc++) {
        const int cur = kc & 1;
        if (kc + 1 < NCH) { load_stage(1 - cur, kc + 1); CP_COMMIT(); }

        const uint32_t stb = sb + cur * STAGE_B;
#pragma unroll
        for (int ks = 0; ks < 2; ks++) {
            uint32_t a[4][4], bfr[4][2];
            const int kB = ks * 32;
#pragma unroll
            for (int mf = 0; mf < 4; mf++)
                ldsm_x4(a[mf], stb + (wm * 64 + mf * 16 + aRowOff) * 80 + kB + aColB0);
#pragma unroll
            for (int np = 0; np < 2; np++) {
                uint32_t t[4];
                ldsm_x4(t, stb + TILE_B + (wn * 32 + np * 16 + bRowOff) * 80 + kB + bColB0);
                bfr[np * 2][0] = t[0]; bfr[np * 2][1] = t[1];
                bfr[np * 2 + 1][0] = t[2]; bfr[np * 2 + 1][1] = t[3];
            }
#pragma unroll
            for (int mf = 0; mf < 4; mf++)
#pragma unroll
                for (int nf = 0; nf < 4; nf++)
                    mma_f16(acc[mf][nf], a[mf], bfr[nf]);
        }
        if (kc + 1 < NCH) { CP_WAIT0(); __syncthreads(); }
    }

    const float qs = (z == 0) ? 0.125f : 1.0f;
#pragma unroll
    for (int mf = 0; mf < 4; mf++) {
#pragma unroll
        for (int half = 0; half < 2; half++) {
            const int rl = wm * 64 + mf * 16 + (lane >> 2) + half * 8;
            const int j = jbase + rl;
            if (j >= nact) continue;
#pragma unroll
            for (int nf = 0; nf < 4; nf++) {
                const int col = n0 + wn * 32 + nf * 8 + ((lane & 3) << 1);
                float v0 = acc[mf][nf][half * 2 + 0] + bias[col];
                float v1 = acc[mf][nf][half * 2 + 1] + bias[col + 1];
                *(__half2*)(Oq + (size_t)(bb * S_ + j) * DM + col) =
                    __floats2half2_rn(v0 * qs, v1 * qs);
            }
        }
    }
}

// ---------------------------------------------------------------------------
// O-projection GEMM, finer tiles for occupancy: CTA 128 rows x 64 cols,
// 256 threads, 8 warps (4x2), warp tile 32x32, BK=32, pitch 80B, 2-stage.
// grid = (DM/64, 16, B_): live CTAs ~2x MODE-3-of-R15 -> 2 CTAs/SM.
// ---------------------------------------------------------------------------
#define OT_A 10240                        // 128*80
#define OT_B 5120                         // 64*80
#define OSTG (OT_A + OT_B)                // 15360
#define OSMEM (2 * OSTG)                  // 30720

__global__ __launch_bounds__(256, 2) void gemm_o(
    const float* __restrict__ bias, float* __restrict__ Cout)
{
    extern __shared__ char smem[];
    const uint32_t sb = smem_u32(smem);
    const int tid = threadIdx.x;
    const int wid = tid >> 5;
    const int lane = tid & 31;
    const int wm = wid >> 1;       // 0..3 (32-row slices)
    const int wn = wid & 1;        // 0..1 (32-col slices)
    const int n0 = blockIdx.x * 64;
    const int bb = blockIdx.z;
    const int jbase = blockIdx.y * 128;
    const int nact = g_nact[bb];
    if (jbase >= nact) return;

    float acc[2][4][4];
#pragma unroll
    for (int i = 0; i < 2; i++)
#pragma unroll
        for (int j = 0; j < 4; j++)
#pragma unroll
            for (int e = 0; e < 4; e++) acc[i][j][e] = 0.f;

    // loaders: A row lr = tid>>1, chunks (tid&1)*2 + {0,1}; B row rb = tid>>2,
    // chunk cb = tid&3 (one per thread).
    const int lr = tid >> 1;
    const int lc0 = (tid & 1) * 2;
    const int rb = tid >> 2;
    const int cb = tid & 3;

    size_t rowA;
    {
        int j = jbase + lr;
        if (j >= nact) j = nact - 1;
        rowA = (size_t)(bb * S_ + j) * DM;   // compacted ctx rows, dense
    }
    const size_t rowB = (size_t)(n0 + rb) * DM;
    const __half* Bw = g_w[3];

    auto load_stage = [&](int st, int kc) {
        const int k0 = kc * 32;
        const uint32_t sbase = sb + st * OSTG;
#pragma unroll
        for (int c = 0; c < 2; c++) {
            const int ch = lc0 + c;
            cp16(sbase + lr * 80 + ch * 16, g_c + rowA + k0 + ch * 8);
        }
        cp16(sbase + OT_A + rb * 80 + cb * 16, Bw + rowB + k0 + cb * 8);
    };

    const int aRowOff = lane & 15;
    const int aColB0 = ((lane >> 4) << 3) * 2;
    const int bRowOff = (lane & 7) + ((lane >> 4) << 3);
    const int bColB0 = (((lane >> 3) & 1) << 3) * 2;

    load_stage(0, 0);
    CP_COMMIT();
    CP_WAIT0();
    __syncthreads();

    const int NCH = DM / 32;
    for (int kc = 0; kc < NCH; kc++) {
        const int cur = kc & 1;
        if (kc + 1 < NCH) { load_stage(1 - cur, kc + 1); CP_COMMIT(); }

        const uint32_t stb = sb + cur * OSTG;
#pragma unroll
        for (int ks = 0; ks < 2; ks++) {
            uint32_t a[2][4], bfr[4][2];
            const int kB = ks * 32;
#pragma unroll
            for (int mf = 0; mf < 2; mf++)
                ldsm_x4(a[mf], stb + (wm * 32 + mf * 16 + aRowOff) * 80 + kB + aColB0);
#pragma unroll
            for (int np = 0; np < 2; np++) {
                uint32_t t[4];
                ldsm_x4(t, stb + OT_A + (wn * 32 + np * 16 + bRowOff) * 80 + kB + bColB0);
                bfr[np * 2][0] = t[0]; bfr[np * 2][1] = t[1];
                bfr[np * 2 + 1][0] = t[2]; bfr[np * 2 + 1][1] = t[3];
            }
#pragma unroll
            for (int mf = 0; mf < 2; mf++)
#pragma unroll
                for (int nf = 0; nf < 4; nf++)
                    mma_f16(acc[mf][nf], a[mf], bfr[nf]);
        }
        if (kc + 1 < NCH) { CP_WAIT0(); __syncthreads(); }
    }

#pragma unroll
    for (int mf = 0; mf < 2; mf++) {
#pragma unroll
        for (int half = 0; half < 2; half++) {
            const int rl = wm * 32 + mf * 16 + (lane >> 2) + half * 8;
            const int j = jbase + rl;
            if (j >= nact) continue;
            const int tok = g_idx[bb * S_ + j];
#pragma unroll
            for (int nf = 0; nf < 4; nf++) {
                const int col = n0 + wn * 32 + nf * 8 + ((lane & 3) << 1);
                float2 o;
                o.x = acc[mf][nf][half * 2 + 0] + bias[col];
                o.y = acc[mf][nf][half * 2 + 1] + bias[col + 1];
                *(float2*)(Cout + (size_t)(bb * S_ + tok) * DM + col) = o;
            }
        }
    }
}

// ---------------------------------------------------------------------------
// fp16 mma.sync flash attention, compacted Q and K, fixed m=0 softmax.
// Inactive keys fold exactly: l starts at (S - nact). Padded keys -> -1e30.
// ---------------------------------------------------------------------------
#define AT_STG0  18432
#define AT_STGSZ 18432
#define AT_SMEM  (AT_STG0 + 2 * AT_STGSZ)   // 55296
#define PITCHB   144

__device__ __forceinline__ void prefetch_kv(uint32_t sb, int b, int kt, int st,
                                            int dcol, int tid, int nact)
{
    const uint32_t stg = sb + AT_STG0 + st * AT_STGSZ;
#pragma unroll
    for (int t = 0; t < 4; t++) {
        const __half* src = (t < 2) ? g_k : g_v;
        const int arr = t >> 1;
        const int rem = (tid + t * 256) - arr * 512;   // 0..511
        const int row = rem >> 3, ch = rem & 7;
        int j = kt * 64 + row;
        if (j >= nact) j = nact - 1;
        cp16(stg + arr * 9216 + row * PITCHB + ch * 16,
             src + (size_t)(b * S_ + j) * DM + dcol + ch * 8);
    }
}

__global__ __launch_bounds__(256, 2) void attn_mma()
{
    extern __shared__ char smem[];
    const uint32_t sb = smem_u32(smem);
    const int tid = threadIdx.x, wid = tid >> 5, lane = tid & 31;
    const int qt = blockIdx.x, h = blockIdx.y, b = blockIdx.z;
    const int nact = g_nact[b];
    if (qt * 128 >= nact) return;
    const int dcol = h * HD;
    const int nkt = (nact + 63) >> 6;

#pragma unroll
    for (int t = 0; t < 4; t++) {
        const int rem = tid + t * 256;
        const int row = rem >> 3, ch = rem & 7;
        int j = qt * 128 + row;
        if (j >= nact) j = nact - 1;
        cp16(sb + row * PITCHB + ch * 16,
             g_q + (size_t)(b * S_ + j) * DM + dcol + ch * 8);
    }
    prefetch_kv(sb, b, 0, 0, dcol, tid, nact);
    CP_COMMIT();
    CP_WAIT0();
    __syncthreads();

    uint32_t qa[4][4];
    {
        const int aRow = lane & 15;
        const int aCol = (lane >> 4) * 16;
#pragma unroll
        for (int kk = 0; kk < 4; kk++)
            ldsm_x4(qa[kk], sb + (wid * 16 + aRow) * PITCHB + kk * 32 + aCol);
    }

    float Oc[8][4];
#pragma unroll
    for (int j = 0; j < 8; j++)
#pragma unroll
        for (int e = 0; e < 4; e++) Oc[j][e] = 0.f;
    float lr0 = (float)(S_ - nact), lr1 = (float)(S_ - nact);

    const int bRowK = (lane & 7) + ((lane >> 4) << 3);
    const int bColK = ((lane >> 3) & 1) * 16;
    const int vRow = (lane & 7) + (((lane >> 3) & 1) << 3);
    const int vColB = ((lane >> 4) << 3) * 2;

    for (int kt = 0; kt < nkt; kt++) {
        if (kt + 1 < nkt) {
            prefetch_kv(sb, b, kt + 1, (kt + 1) & 1, dcol, tid, nact);
            CP_COMMIT();
            CP_WAIT1();
        } else {
            CP_WAIT0();
        }
        __syncthreads();
        const uint32_t stg = sb + AT_STG0 + (kt & 1) * AT_STGSZ;

        float sacc[8][4];
#pragma unroll
        for (int j = 0; j < 8; j++)
#pragma unroll
            for (int e = 0; e < 4; e++) sacc[j][e] = 0.f;

#pragma unroll
        for (int kg = 0; kg < 4; kg++) {
#pragma unroll
            for (int kk = 0; kk < 4; kk++) {
                uint32_t t[4];
                ldsm_x4(t, stg + (kg * 16 + bRowK) * PITCHB + kk * 32 + bColK);
                uint32_t b0[2] = {t[0], t[1]}, b1[2] = {t[2], t[3]};
                mma_f16(sacc[2 * kg],     qa[kk], b0);
                mma_f16(sacc[2 * kg + 1], qa[kk], b1);
            }
        }

        if (kt == nkt - 1) {
            const int kbase = kt * 64;
#pragma unroll
            for (int jj = 0; jj < 8; jj++) {
                const int kc0 = kbase + (jj >> 1) * 16 + (jj & 1) * 8 + ((lane & 3) << 1);
                if (kc0 >= nact)     { sacc[jj][0] = -1e30f; sacc[jj][2] = -1e30f; }
                if (kc0 + 1 >= nact) { sacc[jj][1] = -1e30f; sacc[jj][3] = -1e30f; }
            }
        }

        float sum0 = 0.f, sum1 = 0.f;
#pragma unroll
        for (int j = 0; j < 8; j++) {
            sacc[j][0] = __expf(sacc[j][0]);
            sacc[j][1] = __expf(sacc[j][1]);
            sacc[j][2] = __expf(sacc[j][2]);
            sacc[j][3] = __expf(sacc[j][3]);
            sum0 += sacc[j][0] + sacc[j][1];
            sum1 += sacc[j][2] + sacc[j][3];
        }
        sum0 += __shfl_xor_sync(0xffffffffu, sum0, 1);
        sum0 += __shfl_xor_sync(0xffffffffu, sum0, 2);
        sum1 += __shfl_xor_sync(0xffffffffu, sum1, 1);
        sum1 += __shfl_xor_sync(0xffffffffu, sum1, 2);
        lr0 += sum0;
        lr1 += sum1;

#pragma unroll
        for (int kk2 = 0; kk2 < 4; kk2++) {
            uint32_t ap[4];
#pragma unroll
            for (int f = 0; f < 2; f++) {
                const float* p = sacc[2 * kk2 + f];
                ap[2 * f]     = pack2h(p[0], p[1]);
                ap[2 * f + 1] = pack2h(p[2], p[3]);
            }
#pragma unroll
            for (int ng2 = 0; ng2 < 4; ng2++) {
                uint32_t t[4];
                ldsm_x4t(t, stg + 9216 + (kk2 * 16 + vRow) * PITCHB + ng2 * 32 + vColB);
                uint32_t b0[2] = {t[0], t[1]}, b1[2] = {t[2], t[3]};
                mma_f16(Oc[2 * ng2],     ap, b0);
                mma_f16(Oc[2 * ng2 + 1], ap, b1);
            }
        }
        __syncthreads();
    }

    const float inv0 = 1.f / lr0;
    const float inv1 = 1.f / lr1;
    const int jl = wid * 16 + (lane >> 2);
    const int j0 = qt * 128 + jl;
    const int j1 = j0 + 8;
#pragma unroll
    for (int j = 0; j < 8; j++) {
        const int col = dcol + j * 8 + ((lane & 3) << 1);
        if (j0 < nact)
            *(__half2*)(g_c + (size_t)(b * S_ + j0) * DM + col) =
                __floats2half2_rn(Oc[j][0] * inv0, Oc[j][1] * inv0);
        if (j1 < nact)
            *(__half2*)(g_c + (size_t)(b * S_ + j1) * DM + col) =
                __floats2half2_rn(Oc[j][2] * inv1, Oc[j][3] * inv1);
    }
}

// ---------------------------------------------------------------------------
extern "C" void kernel_launch(void* const* d_in, const int* in_sizes, int n_in,
                              void* d_out, int out_size)
{
    const float* x    = (const float*)d_in[0];
    const int*   gate = (const int*)  d_in[1];
    const float* Wq   = (const float*)d_in[2];
    const float* bq   = (const float*)d_in[3];
    const float* Wk   = (const float*)d_in[4];
    const float* bk   = (const float*)d_in[5];
    const float* Wv   = (const float*)d_in[6];
    const float* bv   = (const float*)d_in[7];
    const float* Wo   = (const float*)d_in[8];
    const float* bo   = (const float*)d_in[9];
    float* out = (float*)d_out;

    cudaFuncSetAttribute(gemm_qkv, cudaFuncAttributeMaxDynamicSharedMemorySize, GSMEM_TOT);
    cudaFuncSetAttribute(gemm_o, cudaFuncAttributeMaxDynamicSharedMemorySize, OSMEM);
    cudaFuncSetAttribute(attn_mma, cudaFuncAttributeMaxDynamicSharedMemorySize, AT_SMEM);

    prologue<<<8194, 256>>>(x, out, gate, Wq, Wk, Wv, Wo);

    gemm_qkv<<<dim3(DM / 128, B_ * 16, 3), 256, GSMEM_TOT>>>(bq, bk, bv);

    attn_mma<<<dim3(S_ / 128, HEADS, B_), 256, AT_SMEM>>>();

    gemm_o<<<dim3(DM / 64, 16, B_), 256, OSMEM>>>(bo, out);
}

// round 17
// speedup vs baseline: 1.1257x; 1.1257x over previous
#include <cuda_runtime.h>
#include <cuda_fp16.h>
#include <cstdint>
#include <cstddef>

#define DM 1024
#define HEADS 16
#define HD 64
#define B_ 2
#define S_ 2048
#define MTOT 4096   // B*S

// ---------------------------------------------------------------------------
// Scratch. q/k/v/ctx stored COMPACTED (active rows only).
// ---------------------------------------------------------------------------
__device__ __half g_x[MTOT * DM];
__device__ __half g_q[MTOT * DM];   // pre-scaled by 1/8
__device__ __half g_k[MTOT * DM];
__device__ __half g_v[MTOT * DM];
__device__ __half g_c[MTOT * DM];
__device__ __half g_w[4][DM * DM];  // W^T, [n][k]
__device__ float g_p0[MTOT * DM];   // O-proj split-K partials
__device__ float g_p1[MTOT * DM];
__device__ int g_nact[B_];
__device__ int g_idx[B_ * S_];

// ---------------------------------------------------------------------------
// sm_100-safe PTX helpers
// ---------------------------------------------------------------------------
__device__ __forceinline__ uint32_t smem_u32(const void* p) {
    uint32_t a;
    asm("{ .reg .u64 t; cvta.to.shared.u64 t, %1; cvt.u32.u64 %0, t; }"
        : "=r"(a) : "l"(p));
    return a;
}
__device__ __forceinline__ void ldsm_x4(uint32_t* r, uint32_t addr) {
    asm volatile("ldmatrix.sync.aligned.m8n8.x4.shared.b16 {%0,%1,%2,%3}, [%4];"
                 : "=r"(r[0]), "=r"(r[1]), "=r"(r[2]), "=r"(r[3]) : "r"(addr));
}
__device__ __forceinline__ void ldsm_x4t(uint32_t* r, uint32_t addr) {
    asm volatile("ldmatrix.sync.aligned.m8n8.x4.trans.shared.b16 {%0,%1,%2,%3}, [%4];"
                 : "=r"(r[0]), "=r"(r[1]), "=r"(r[2]), "=r"(r[3]) : "r"(addr));
}
__device__ __forceinline__ void mma_f16(float* d, const uint32_t* a, const uint32_t* b) {
    asm volatile(
        "mma.sync.aligned.m16n8k16.row.col.f32.f16.f16.f32 "
        "{%0,%1,%2,%3},{%4,%5,%6,%7},{%8,%9},{%0,%1,%2,%3};"
        : "+f"(d[0]), "+f"(d[1]), "+f"(d[2]), "+f"(d[3])
        : "r"(a[0]), "r"(a[1]), "r"(a[2]), "r"(a[3]), "r"(b[0]), "r"(b[1]));
}
__device__ __forceinline__ void cp16(uint32_t s, const void* g) {
    asm volatile("cp.async.cg.shared.global [%0], [%1], 16;" :: "r"(s), "l"(g));
}
#define CP_COMMIT() asm volatile("cp.async.commit_group;" ::: "memory")
#define CP_WAIT0()  asm volatile("cp.async.wait_group 0;" ::: "memory")
#define CP_WAIT1()  asm volatile("cp.async.wait_group 1;" ::: "memory")

__device__ __forceinline__ uint32_t pack2h(float lo, float hi) {
    uint32_t r;
    asm("cvt.rn.f16x2.f32 %0, %1, %2;" : "=r"(r) : "f"(hi), "f"(lo));
    return r;
}

// ---------------------------------------------------------------------------
// Fused prologue (R15, proven): 8194 CTAs x 256.
// ---------------------------------------------------------------------------
__global__ __launch_bounds__(256) void prologue(
    const float* __restrict__ x, float* __restrict__ out,
    const int* __restrict__ gate,
    const float* __restrict__ W0, const float* __restrict__ W1,
    const float* __restrict__ W2, const float* __restrict__ W3)
{
    const int bid = blockIdx.x;
    const int tid = threadIdx.x;

    if (bid < 4096) {
        __shared__ float t[32][33];
        const int z = bid >> 10;
        const int tile = bid & 1023;
        const float* W = (z == 0) ? W0 : (z == 1) ? W1 : (z == 2) ? W2 : W3;
        const int n0 = (tile & 31) * 32;
        const int k0 = (tile >> 5) * 32;
        const int tx = tid & 31, ty = tid >> 5;
#pragma unroll
        for (int i = 0; i < 4; i++)
            t[ty + i * 8][tx] = W[(size_t)(k0 + ty + i * 8) * DM + n0 + tx];
        __syncthreads();
        __half* p = g_w[z];
#pragma unroll
        for (int i = 0; i < 4; i++)
            p[(size_t)(n0 + ty + i * 8) * DM + k0 + tx] =
                __float2half(t[tx][ty + i * 8]);
    } else if (bid < 8192) {
        const int i = ((bid - 4096) * 256 + tid) * 4;
        float4 v = *(const float4*)(x + i);
        *(float4*)(out + i) = v;
        *(__half2*)(g_x + i)     = __floats2half2_rn(v.x, v.y);
        *(__half2*)(g_x + i + 2) = __floats2half2_rn(v.z, v.w);
    } else {
        __shared__ int cnt[256];
        const int b = bid - 8192;
        const int base = b * S_ + tid * 8;
        int gv[8];
        int c = 0;
#pragma unroll
        for (int i = 0; i < 8; i++) { gv[i] = gate[base + i]; c += gv[i]; }
        cnt[tid] = c;
        __syncthreads();
        for (int off = 1; off < 256; off <<= 1) {
            int t = (tid >= off) ? cnt[tid - off] : 0;
            __syncthreads();
            cnt[tid] += t;
            __syncthreads();
        }
        int o = cnt[tid] - c;
        if (tid == 255) g_nact[b] = cnt[255];
#pragma unroll
        for (int i = 0; i < 8; i++)
            if (gv[i]) g_idx[b * S_ + (o++)] = tid * 8 + i;
    }
}

// ---------------------------------------------------------------------------
// QKV GEMM — exact R9/R15 config (measured best). CTA 128x128, 8 warps (2x4),
// warp tile 64x32, BK=32, pitch 80B. grid = (8, B_*16, 3).
// ---------------------------------------------------------------------------
#define TILE_B 10240
#define STAGE_B (2 * TILE_B)              // 20480
#define GSMEM_TOT (2 * STAGE_B)           // 40960

__global__ __launch_bounds__(256, 2) void gemm_qkv(
    const float* __restrict__ bias0, const float* __restrict__ bias1,
    const float* __restrict__ bias2)
{
    extern __shared__ char smem[];
    const uint32_t sb = smem_u32(smem);
    const int tid = threadIdx.x;
    const int wid = tid >> 5;
    const int lane = tid & 31;
    const int wm = wid >> 2;
    const int wn = wid & 3;
    const int n0 = blockIdx.x * 128;

    const int bb = blockIdx.y >> 4;
    const int jbase = (blockIdx.y & 15) * 128;
    const int nact = g_nact[bb];
    if (jbase >= nact) return;
    const int z = blockIdx.z;

    const __half* Bw = g_w[z];
    const float* bias = (z == 0) ? bias0 : (z == 1) ? bias1 : bias2;
    __half* Oq = (z == 0) ? g_q : (z == 1) ? g_k : g_v;

    float acc[4][4][4];
#pragma unroll
    for (int i = 0; i < 4; i++)
#pragma unroll
        for (int j = 0; j < 4; j++)
#pragma unroll
            for (int e = 0; e < 4; e++) acc[i][j][e] = 0.f;

    const int lrow = tid >> 1;
    const int lc0 = (tid & 1) * 2;

    size_t rowA;
    {
        int j = jbase + lrow;
        if (j >= nact) j = nact - 1;
        rowA = (size_t)(bb * S_ + g_idx[bb * S_ + j]) * DM;
    }
    const size_t rowB = (size_t)(n0 + lrow) * DM;

    auto load_stage = [&](int st, int kc) {
        const int k0 = kc * 32;
        const uint32_t sbase = sb + st * STAGE_B;
#pragma unroll
        for (int c = 0; c < 2; c++) {
            const int ch = lc0 + c;
            const uint32_t so = lrow * 80 + ch * 16;
            cp16(sbase + so,          g_x + rowA + k0 + ch * 8);
            cp16(sbase + TILE_B + so, Bw + rowB + k0 + ch * 8);
        }
    };

    const int aRowOff = lane & 15;
    const int aColB0 = ((lane >> 4) << 3) * 2;
    const int bRowOff = (lane & 7) + ((lane >> 4) << 3);
    const int bColB0 = (((lane >> 3) & 1) << 3) * 2;

    load_stage(0, 0);
    CP_COMMIT();
    CP_WAIT0();
    __syncthreads();

    const int NCH = DM / 32;
    for (int kc = 0; kc < NCH; kc++) {
        const int cur = kc & 1;
        if (kc + 1 < NCH) { load_stage(1 - cur, kc + 1); CP_COMMIT(); }

        const uint32_t stb = sb + cur * STAGE_B;
#pragma unroll
        for (int ks = 0; ks < 2; ks++) {
            uint32_t a[4][4], bfr[4][2];
            const int kB = ks * 32;
#pragma unroll
            for (int mf = 0; mf < 4; mf++)
                ldsm_x4(a[mf], stb + (wm * 64 + mf * 16 + aRowOff) * 80 + kB + aColB0);
#pragma unroll
            for (int np = 0; np < 2; np++) {
                uint32_t t[4];
                ldsm_x4(t, stb + TILE_B + (wn * 32 + np * 16 + bRowOff) * 80 + kB + bColB0);
                bfr[np * 2][0] = t[0]; bfr[np * 2][1] = t[1];
                bfr[np * 2 + 1][0] = t[2]; bfr[np * 2 + 1][1] = t[3];
            }
#pragma unroll
            for (int mf = 0; mf < 4; mf++)
#pragma unroll
                for (int nf = 0; nf < 4; nf++)
                    mma_f16(acc[mf][nf], a[mf], bfr[nf]);
        }
        if (kc + 1 < NCH) { CP_WAIT0(); __syncthreads(); }
    }

    const float qs = (z == 0) ? 0.125f : 1.0f;
#pragma unroll
    for (int mf = 0; mf < 4; mf++) {
#pragma unroll
        for (int half = 0; half < 2; half++) {
            const int rl = wm * 64 + mf * 16 + (lane >> 2) + half * 8;
            const int j = jbase + rl;
            if (j >= nact) continue;
#pragma unroll
            for (int nf = 0; nf < 4; nf++) {
                const int col = n0 + wn * 32 + nf * 8 + ((lane & 3) << 1);
                float v0 = acc[mf][nf][half * 2 + 0] + bias[col];
                float v1 = acc[mf][nf][half * 2 + 1] + bias[col + 1];
                *(__half2*)(Oq + (size_t)(bb * S_ + j) * DM + col) =
                    __floats2half2_rn(v0 * qs, v1 * qs);
            }
        }
    }
}

// ---------------------------------------------------------------------------
// O-projection split-K GEMM: SAME proven 128x128 tile / inner loop, but each
// CTA covers half of K (512). grid = (8, 16, B_*2); z = batch*2 + khalf.
// ~272 live CTAs -> full 2-CTA/SM wave. Partials in fp32 g_p0/g_p1.
// ---------------------------------------------------------------------------
__global__ __launch_bounds__(256, 2) void gemm_o_part()
{
    extern __shared__ char smem[];
    const uint32_t sb = smem_u32(smem);
    const int tid = threadIdx.x;
    const int wid = tid >> 5;
    const int lane = tid & 31;
    const int wm = wid >> 2;
    const int wn = wid & 3;
    const int n0 = blockIdx.x * 128;
    const int bb = blockIdx.z >> 1;
    const int kh = blockIdx.z & 1;
    const int jbase = blockIdx.y * 128;
    const int nact = g_nact[bb];
    if (jbase >= nact) return;

    const __half* Bw = g_w[3];
    float* P = kh ? g_p1 : g_p0;
    const int koff = kh * 512;

    float acc[4][4][4];
#pragma unroll
    for (int i = 0; i < 4; i++)
#pragma unroll
        for (int j = 0; j < 4; j++)
#pragma unroll
            for (int e = 0; e < 4; e++) acc[i][j][e] = 0.f;

    const int lrow = tid >> 1;
    const int lc0 = (tid & 1) * 2;

    size_t rowA;
    {
        int j = jbase + lrow;
        if (j >= nact) j = nact - 1;
        rowA = (size_t)(bb * S_ + j) * DM;   // compacted ctx, dense
    }
    const size_t rowB = (size_t)(n0 + lrow) * DM;

    auto load_stage = [&](int st, int kc) {
        const int k0 = koff + kc * 32;
        const uint32_t sbase = sb + st * STAGE_B;
#pragma unroll
        for (int c = 0; c < 2; c++) {
            const int ch = lc0 + c;
            const uint32_t so = lrow * 80 + ch * 16;
            cp16(sbase + so,          g_c + rowA + k0 + ch * 8);
            cp16(sbase + TILE_B + so, Bw + rowB + k0 + ch * 8);
        }
    };

    const int aRowOff = lane & 15;
    const int aColB0 = ((lane >> 4) << 3) * 2;
    const int bRowOff = (lane & 7) + ((lane >> 4) << 3);
    const int bColB0 = (((lane >> 3) & 1) << 3) * 2;

    load_stage(0, 0);
    CP_COMMIT();
    CP_WAIT0();
    __syncthreads();

    const int NCH = 512 / 32;   // 16
    for (int kc = 0; kc < NCH; kc++) {
        const int cur = kc & 1;
        if (kc + 1 < NCH) { load_stage(1 - cur, kc + 1); CP_COMMIT(); }

        const uint32_t stb = sb + cur * STAGE_B;
#pragma unroll
        for (int ks = 0; ks < 2; ks++) {
            uint32_t a[4][4], bfr[4][2];
            const int kB = ks * 32;
#pragma unroll
            for (int mf = 0; mf < 4; mf++)
                ldsm_x4(a[mf], stb + (wm * 64 + mf * 16 + aRowOff) * 80 + kB + aColB0);
#pragma unroll
            for (int np = 0; np < 2; np++) {
                uint32_t t[4];
                ldsm_x4(t, stb + TILE_B + (wn * 32 + np * 16 + bRowOff) * 80 + kB + bColB0);
                bfr[np * 2][0] = t[0]; bfr[np * 2][1] = t[1];
                bfr[np * 2 + 1][0] = t[2]; bfr[np * 2 + 1][1] = t[3];
            }
#pragma unroll
            for (int mf = 0; mf < 4; mf++)
#pragma unroll
                for (int nf = 0; nf < 4; nf++)
                    mma_f16(acc[mf][nf], a[mf], bfr[nf]);
        }
        if (kc + 1 < NCH) { CP_WAIT0(); __syncthreads(); }
    }

#pragma unroll
    for (int mf = 0; mf < 4; mf++) {
#pragma unroll
        for (int half = 0; half < 2; half++) {
            const int rl = wm * 64 + mf * 16 + (lane >> 2) + half * 8;
            const int j = jbase + rl;
            if (j >= nact) continue;
#pragma unroll
            for (int nf = 0; nf < 4; nf++) {
                const int col = n0 + wn * 32 + nf * 8 + ((lane & 3) << 1);
                float2 o;
                o.x = acc[mf][nf][half * 2 + 0];
                o.y = acc[mf][nf][half * 2 + 1];
                *(float2*)(P + (size_t)(bb * S_ + j) * DM + col) = o;
            }
        }
    }
}

// Combine split-K partials + bias, scatter to out via g_idx.
// grid (S_, B_): CTA = one compacted row; inactive rows exit.
__global__ __launch_bounds__(256) void reduce_o(
    const float* __restrict__ bias, float* __restrict__ out)
{
    const int j = blockIdx.x, b = blockIdx.y;
    if (j >= g_nact[b]) return;
    const int tok = g_idx[b * S_ + j];
    const size_t rsrc = (size_t)(b * S_ + j) * DM;
    const size_t rdst = (size_t)(b * S_ + tok) * DM;
    const int i = threadIdx.x * 4;
    float4 p0 = *(const float4*)(g_p0 + rsrc + i);
    float4 p1 = *(const float4*)(g_p1 + rsrc + i);
    float4 bs = *(const float4*)(bias + i);
    float4 o;
    o.x = p0.x + p1.x + bs.x;
    o.y = p0.y + p1.y + bs.y;
    o.z = p0.z + p1.z + bs.z;
    o.w = p0.w + p1.w + bs.w;
    *(float4*)(out + rdst + i) = o;
}

// ---------------------------------------------------------------------------
// fp16 mma.sync flash attention (R15, proven): compacted Q/K, fixed m=0.
// ---------------------------------------------------------------------------
#define AT_STG0  18432
#define AT_STGSZ 18432
#define AT_SMEM  (AT_STG0 + 2 * AT_STGSZ)   // 55296
#define PITCHB   144

__device__ __forceinline__ void prefetch_kv(uint32_t sb, int b, int kt, int st,
                                            int dcol, int tid, int nact)
{
    const uint32_t stg = sb + AT_STG0 + st * AT_STGSZ;
#pragma unroll
    for (int t = 0; t < 4; t++) {
        const __half* src = (t < 2) ? g_k : g_v;
        const int arr = t >> 1;
        const int rem = (tid + t * 256) - arr * 512;
        const int row = rem >> 3, ch = rem & 7;
        int j = kt * 64 + row;
        if (j >= nact) j = nact - 1;
        cp16(stg + arr * 9216 + row * PITCHB + ch * 16,
             src + (size_t)(b * S_ + j) * DM + dcol + ch * 8);
    }
}

__global__ __launch_bounds__(256, 2) void attn_mma()
{
    extern __shared__ char smem[];
    const uint32_t sb = smem_u32(smem);
    const int tid = threadIdx.x, wid = tid >> 5, lane = tid & 31;
    const int qt = blockIdx.x, h = blockIdx.y, b = blockIdx.z;
    const int nact = g_nact[b];
    if (qt * 128 >= nact) return;
    const int dcol = h * HD;
    const int nkt = (nact + 63) >> 6;

#pragma unroll
    for (int t = 0; t < 4; t++) {
        const int rem = tid + t * 256;
        const int row = rem >> 3, ch = rem & 7;
        int j = qt * 128 + row;
        if (j >= nact) j = nact - 1;
        cp16(sb + row * PITCHB + ch * 16,
             g_q + (size_t)(b * S_ + j) * DM + dcol + ch * 8);
    }
    prefetch_kv(sb, b, 0, 0, dcol, tid, nact);
    CP_COMMIT();
    CP_WAIT0();
    __syncthreads();

    uint32_t qa[4][4];
    {
        const int aRow = lane & 15;
        const int aCol = (lane >> 4) * 16;
#pragma unroll
        for (int kk = 0; kk < 4; kk++)
            ldsm_x4(qa[kk], sb + (wid * 16 + aRow) * PITCHB + kk * 32 + aCol);
    }

    float Oc[8][4];
#pragma unroll
    for (int j = 0; j < 8; j++)
#pragma unroll
        for (int e = 0; e < 4; e++) Oc[j][e] = 0.f;
    float lr0 = (float)(S_ - nact), lr1 = (float)(S_ - nact);

    const int bRowK = (lane & 7) + ((lane >> 4) << 3);
    const int bColK = ((lane >> 3) & 1) * 16;
    const int vRow = (lane & 7) + (((lane >> 3) & 1) << 3);
    const int vColB = ((lane >> 4) << 3) * 2;

    for (int kt = 0; kt < nkt; kt++) {
        if (kt + 1 < nkt) {
            prefetch_kv(sb, b, kt + 1, (kt + 1) & 1, dcol, tid, nact);
            CP_COMMIT();
            CP_WAIT1();
        } else {
            CP_WAIT0();
        }
        __syncthreads();
        const uint32_t stg = sb + AT_STG0 + (kt & 1) * AT_STGSZ;

        float sacc[8][4];
#pragma unroll
        for (int j = 0; j < 8; j++)
#pragma unroll
            for (int e = 0; e < 4; e++) sacc[j][e] = 0.f;

#pragma unroll
        for (int kg = 0; kg < 4; kg++) {
#pragma unroll
            for (int kk = 0; kk < 4; kk++) {
                uint32_t t[4];
                ldsm_x4(t, stg + (kg * 16 + bRowK) * PITCHB + kk * 32 + bColK);
                uint32_t b0[2] = {t[0], t[1]}, b1[2] = {t[2], t[3]};
                mma_f16(sacc[2 * kg],     qa[kk], b0);
                mma_f16(sacc[2 * kg + 1], qa[kk], b1);
            }
        }

        if (kt == nkt - 1) {
            const int kbase = kt * 64;
#pragma unroll
            for (int jj = 0; jj < 8; jj++) {
                const int kc0 = kbase + (jj >> 1) * 16 + (jj & 1) * 8 + ((lane & 3) << 1);
                if (kc0 >= nact)     { sacc[jj][0] = -1e30f; sacc[jj][2] = -1e30f; }
                if (kc0 + 1 >= nact) { sacc[jj][1] = -1e30f; sacc[jj][3] = -1e30f; }
            }
        }

        float sum0 = 0.f, sum1 = 0.f;
#pragma unroll
        for (int j = 0; j < 8; j++) {
            sacc[j][0] = __expf(sacc[j][0]);
            sacc[j][1] = __expf(sacc[j][1]);
            sacc[j][2] = __expf(sacc[j][2]);
            sacc[j][3] = __expf(sacc[j][3]);
            sum0 += sacc[j][0] + sacc[j][1];
            sum1 += sacc[j][2] + sacc[j][3];
        }
        sum0 += __shfl_xor_sync(0xffffffffu, sum0, 1);
        sum0 += __shfl_xor_sync(0xffffffffu, sum0, 2);
        sum1 += __shfl_xor_sync(0xffffffffu, sum1, 1);
        sum1 += __shfl_xor_sync(0xffffffffu, sum1, 2);
        lr0 += sum0;
        lr1 += sum1;

#pragma unroll
        for (int kk2 = 0; kk2 < 4; kk2++) {
            uint32_t ap[4];
#pragma unroll
            for (int f = 0; f < 2; f++) {
                const float* p = sacc[2 * kk2 + f];
                ap[2 * f]     = pack2h(p[0], p[1]);
                ap[2 * f + 1] = pack2h(p[2], p[3]);
            }
#pragma unroll
            for (int ng2 = 0; ng2 < 4; ng2++) {
                uint32_t t[4];
                ldsm_x4t(t, stg + 9216 + (kk2 * 16 + vRow) * PITCHB + ng2 * 32 + vColB);
                uint32_t b0[2] = {t[0], t[1]}, b1[2] = {t[2], t[3]};
                mma_f16(Oc[2 * ng2],     ap, b0);
                mma_f16(Oc[2 * ng2 + 1], ap, b1);
            }
        }
        __syncthreads();
    }

    const float inv0 = 1.f / lr0;
    const float inv1 = 1.f / lr1;
    const int jl = wid * 16 + (lane >> 2);
    const int j0 = qt * 128 + jl;
    const int j1 = j0 + 8;
#pragma unroll
    for (int j = 0; j < 8; j++) {
        const int col = dcol + j * 8 + ((lane & 3) << 1);
        if (j0 < nact)
            *(__half2*)(g_c + (size_t)(b * S_ + j0) * DM + col) =
                __floats2half2_rn(Oc[j][0] * inv0, Oc[j][1] * inv0);
        if (j1 < nact)
            *(__half2*)(g_c + (size_t)(b * S_ + j1) * DM + col) =
                __floats2half2_rn(Oc[j][2] * inv1, Oc[j][3] * inv1);
    }
}

// ---------------------------------------------------------------------------
extern "C" void kernel_launch(void* const* d_in, const int* in_sizes, int n_in,
                              void* d_out, int out_size)
{
    const float* x    = (const float*)d_in[0];
    const int*   gate = (const int*)  d_in[1];
    const float* Wq   = (const float*)d_in[2];
    const float* bq   = (const float*)d_in[3];
    const float* Wk   = (const float*)d_in[4];
    const float* bk   = (const float*)d_in[5];
    const float* Wv   = (const float*)d_in[6];
    const float* bv   = (const float*)d_in[7];
    const float* Wo   = (const float*)d_in[8];
    const float* bo   = (const float*)d_in[9];
    float* out = (float*)d_out;

    cudaFuncSetAttribute(gemm_qkv, cudaFuncAttributeMaxDynamicSharedMemorySize, GSMEM_TOT);
    cudaFuncSetAttribute(gemm_o_part, cudaFuncAttributeMaxDynamicSharedMemorySize, GSMEM_TOT);
    cudaFuncSetAttribute(attn_mma, cudaFuncAttributeMaxDynamicSharedMemorySize, AT_SMEM);

    prologue<<<8194, 256>>>(x, out, gate, Wq, Wk, Wv, Wo);

    gemm_qkv<<<dim3(DM / 128, B_ * 16, 3), 256, GSMEM_TOT>>>(bq, bk, bv);

    attn_mma<<<dim3(S_ / 128, HEADS, B_), 256, AT_SMEM>>>();

    gemm_o_part<<<dim3(DM / 128, 16, B_ * 2), 256, GSMEM_TOT>>>();
    reduce_o<<<dim3(S_, B_), 256>>>(bo, out);
}